// round 10
// baseline (speedup 1.0000x reference)
#include <cuda_runtime.h>
#include <cuda_bf16.h>
#include <math.h>
#include <stdint.h>

// ---------------- problem constants ----------------
#define BATCH 16
#define NPTS 4096
#define NCTR 1024
#define NSAMP 32
#define NROWS (BATCH*NCTR*NSAMP)          // 524288
#define NCTR_TOT (BATCH*NCTR)             // 16384
#define OUT_XYZ_ELEMS (NCTR_TOT*3)        // 49152
#define FPS_NB 16
#define G_NB (BATCH*NPTS/8)               // 8192 (8 pts per 512-thr block)
#define BQ_NB (NCTR_TOT/16)               // 1024 (16 centers per block)

// stats layout (32 slots per channel, sum then sq)
#define SUM0 0
#define SQ0  (64*32)
#define SUM1 (2*64*32)
#define SQ1  (3*64*32)
#define SUM2 (4*64*32)
#define SQ2  (4*64*32 + 128*32)
#define STATS_TOT (4*64*32 + 2*128*32)    // 16384

// affine layout
#define A0 0
#define C0A 64
#define A1 128
#define C1A 192
#define A2 256
#define C2A 384

// ---------------- scratch (static device memory; no allocs) ----------------
__device__ int   g_fps[NCTR_TOT];
__device__ int   g_bidx[NROWS];
__device__ float g_G[BATCH*NPTS*64];      // 16 MB
__device__ float g_C[NCTR_TOT*64];        // 4 MB
__device__ float g_Y1[NROWS*64];          // 134 MB
__device__ float g_mx[NCTR_TOT*128];      // 8 MB
__device__ float g_mn[NCTR_TOT*128];      // 8 MB
__device__ float g_stats[STATS_TOT];
__device__ float g_aff[512];
__device__ volatile int g_prog[BATCH];    // FPS progress (monotone across replays)
__device__ int g_gcnt[BATCH];             // G-completion counter (monotone)

__device__ __forceinline__ unsigned long long u64min(unsigned long long a, unsigned long long b){
    return a < b ? a : b;
}
__device__ __forceinline__ unsigned long long u64max(unsigned long long a, unsigned long long b){
    return a > b ? a : b;
}
__device__ __forceinline__ uint32_t f2tf32(float x){
    uint32_t r; asm("cvt.rna.tf32.f32 %0, %1;" : "=r"(r) : "f"(x)); return r;
}
__device__ __forceinline__ void mma_tf32(float4& d, const uint32_t* a, const uint32_t* b){
    asm volatile("mma.sync.aligned.m16n8k8.row.col.f32.tf32.tf32.f32 "
                 "{%0,%1,%2,%3},{%4,%5,%6,%7},{%8,%9},{%0,%1,%2,%3};"
                 : "+f"(d.x),"+f"(d.y),"+f"(d.z),"+f"(d.w)
                 : "r"(a[0]),"r"(a[1]),"r"(a[2]),"r"(a[3]),"r"(b[0]),"r"(b[1]));
}
// packed f32x2 helpers
__device__ __forceinline__ unsigned long long pk2(float lo, float hi){
    unsigned long long r; asm("mov.b64 %0,{%1,%2};" : "=l"(r) : "f"(lo), "f"(hi)); return r;
}
__device__ __forceinline__ void unpk2(unsigned long long v, float& lo, float& hi){
    asm("mov.b64 {%0,%1},%2;" : "=f"(lo), "=f"(hi) : "l"(v));
}
__device__ __forceinline__ unsigned long long add2(unsigned long long a, unsigned long long b){
    unsigned long long r; asm("add.rn.f32x2 %0,%1,%2;" : "=l"(r) : "l"(a), "l"(b)); return r;
}
__device__ __forceinline__ unsigned long long mul2(unsigned long long a, unsigned long long b){
    unsigned long long r; asm("mul.rn.f32x2 %0,%1,%2;" : "=l"(r) : "l"(a), "l"(b)); return r;
}
__device__ __forceinline__ unsigned long long fma2(unsigned long long a, unsigned long long b, unsigned long long c){
    unsigned long long r; asm("fma.rn.f32x2 %0,%1,%2,%3;" : "=l"(r) : "l"(a), "l"(b), "l"(c)); return r;
}
// k-pair permutation: within each group of 8 k's, place (k, k+4) adjacently
__device__ __forceinline__ int kperm(int k){
    return (k & ~7) | ((k & 3) << 1) | ((k >> 2) & 1);
}

// =====================================================================
// MEGA (512 thr): [0,16) FPS | [16,16+8192) G | rest: ballq+BN0 stats
// =====================================================================
__global__ void __launch_bounds__(512) mega_kernel(
        const float* __restrict__ xyz, const float* __restrict__ feat,
        const float* __restrict__ w0, const float* __restrict__ b0,
        float* __restrict__ out){
    extern __shared__ float sm[];
    int tid = threadIdx.x;
    int bx = blockIdx.x;

    if (bx < FPS_NB){
        // ---------------- FPS: 512 thr, 8 pts/thread, ONE barrier/iter ----------------
        float* sx = sm;               // 4096
        float* sy = sm + 4096;
        float* sz = sm + 8192;
        unsigned long long (*srd)[16] = (unsigned long long(*)[16])(sm + 12288);  // [2][16] u64

        int b = bx;
        const float* xb = xyz + (size_t)b*NPTS*3;

        float pl[8][3], dist[8];
#pragma unroll
        for (int k = 0; k < 8; k++){
            int p = k*512 + tid;
            float x = xb[p*3], y = xb[p*3+1], z = xb[p*3+2];
            pl[k][0]=x; pl[k][1]=y; pl[k][2]=z; dist[k]=INFINITY;
            sx[p]=x; sy[p]=y; sz[p]=z;
        }
        unsigned long long px2[4], py2[4], pz2[4];
#pragma unroll
        for (int j = 0; j < 4; j++){
            px2[j] = pk2(pl[2*j][0], pl[2*j+1][0]);
            py2[j] = pk2(pl[2*j][1], pl[2*j+1][1]);
            pz2[j] = pk2(pl[2*j][2], pl[2*j+1][2]);
        }
        if (tid == 0) g_fps[b*NCTR] = 0;
        float cx = xb[0], cy = xb[1], cz = xb[2];
        __syncthreads();

        int w = tid >> 5;
        for (int t = 1; t < NCTR; t++){
            unsigned long long ncx = pk2(-cx,-cx), ncy = pk2(-cy,-cy), ncz = pk2(-cz,-cz);
            float m = -1.f;
#pragma unroll
            for (int j = 0; j < 4; j++){
                unsigned long long dx = add2(px2[j], ncx);
                unsigned long long dy = add2(py2[j], ncy);
                unsigned long long dz = add2(pz2[j], ncz);
                unsigned long long dd = fma2(dx, dx, fma2(dy, dy, mul2(dz, dz)));
                float dlo, dhi; unpk2(dd, dlo, dhi);
                dist[2*j]   = fminf(dist[2*j],   dlo);
                dist[2*j+1] = fminf(dist[2*j+1], dhi);
                m = fmaxf(m, fmaxf(dist[2*j], dist[2*j+1]));
            }
            // local argmax: smallest global index attaining m
            int cand = 0;
#pragma unroll
            for (int k = 7; k >= 0; k--)
                if (dist[k] == m) cand = k*512 + tid;
            // 64-bit key: high = dist bits (dist >= 0 so bit order == value order),
            // low = ~idx so max-key tie-break picks the smallest index
            unsigned long long key = ((unsigned long long)__float_as_uint(m) << 32)
                                   | (unsigned)(0xFFFFFFFFu - (unsigned)cand);
#pragma unroll
            for (int off = 16; off > 0; off >>= 1)
                key = u64max(key, __shfl_xor_sync(0xffffffffu, key, off));
            int pb = t & 1;
            if ((tid & 31) == 0) srd[pb][w] = key;
            __syncthreads();
            unsigned long long bk = srd[pb][0];
#pragma unroll
            for (int ww = 1; ww < 16; ww++) bk = u64max(bk, srd[pb][ww]);
            int bi2 = (int)(0xFFFFFFFFu - (unsigned)bk);
            cx = sx[bi2]; cy = sy[bi2]; cz = sz[bi2];
            if (tid == 0){
                g_fps[b*NCTR + t] = bi2;
                if ((t & 31) == 31){ __threadfence(); g_prog[b] = t; }
            }
        }
        __syncthreads();

        // new_xyz gather
        for (int i = tid; i < NCTR; i += 512){
            int idx = g_fps[b*NCTR + i];
            size_t o = (size_t)(b*NCTR + i)*3;
            out[o+0] = sx[idx]; out[o+1] = sy[idx]; out[o+2] = sz[idx];
        }
        __syncthreads();

        // C = new_xyz @ W0xT  (used by l1)
        for (int i = tid; i < NCTR*64; i += 512){
            int m2 = i >> 6, c = i & 63;
            const float* wr = w0 + c*67;
            size_t o = (size_t)(b*NCTR + m2)*3;
            float acc = out[o+0]*wr[0];
            acc = fmaf(out[o+1], wr[1], acc);
            acc = fmaf(out[o+2], wr[2], acc);
            g_C[(size_t)(b*NCTR + m2)*64 + c] = acc;
        }
    } else if (bx < FPS_NB + G_NB){
        // ---------------- G branch: 8 points per block ----------------
        int gb = bx - FPS_NB;
        if (gb < 32) g_stats[gb*512 + tid] = 0.f;
        float* w0s = sm;   // 64*67 floats
        for (int i = tid; i < 64*67; i += 512) w0s[i] = w0[i];
        __syncthreads();
        int p = gb*8 + (tid >> 6);
        int c = tid & 63;
        const float* fr = feat + (size_t)p*64;
        const float* wr = w0s + c*67;
        float acc = b0[c];
        acc = fmaf(xyz[p*3+0], wr[0], acc);
        acc = fmaf(xyz[p*3+1], wr[1], acc);
        acc = fmaf(xyz[p*3+2], wr[2], acc);
#pragma unroll 8
        for (int k = 0; k < 64; k++) acc = fmaf(fr[k], wr[3+k], acc);
        g_G[(size_t)p*64 + c] = acc;
        __syncthreads();
        if (tid == 0){
            __threadfence();
            atomicAdd(&g_gcnt[gb >> 9], 1);
        }
    } else {
        // ---------------- ball query + BN0 stats: 16 centers/block ----------------
        float* sxq = sm;                                      // 1024
        float* syq = sm + 1024;
        float* szq = sm + 2048;
        unsigned long long* cbuf = (unsigned long long*)(sm + 3072);  // [16][256]
        unsigned* usel = (unsigned*)(sm + 11264);             // [16][32]
        float* ssum = sm + 11776;                             // 64
        float* ssq  = sm + 11840;                             // 64

        int bq = bx - (FPS_NB + G_NB);
        int b = bq >> 6;
        int q = bq & 63;
        int w = tid >> 5, l = tid & 31;
        int m = q*16 + w;
        int gm = b*NCTR + m;

        if (tid == 0){
            int need = q*16 + 15;
            while (g_prog[b] < need) __nanosleep(128);
            __threadfence();
        }
        __syncthreads();

        int cidx = g_fps[gm];
        const float* xb = xyz + (size_t)b*NPTS*3;
        float qx = xb[cidx*3], qy = xb[cidx*3+1], qz = xb[cidx*3+2];
        const float R2v = (float)(0.2*0.2);

        unsigned long long minkey = ~0ull;
        int cnt = 0;

        for (int ch = 0; ch < 4; ch++){
            __syncthreads();
            for (int i = tid; i < 1024; i += 512){
                int p = ch*1024 + i;
                sxq[i] = xb[p*3]; syq[i] = xb[p*3+1]; szq[i] = xb[p*3+2];
            }
            __syncthreads();
            for (int j = 0; j < 32; j++){
                int pl2 = j*32 + l;
                float dx = qx - sxq[pl2], dy = qy - syq[pl2], dz = qz - szq[pl2];
                float d = fmaf(dx,dx, fmaf(dy,dy, dz*dz));
                int p = ch*1024 + pl2;
                unsigned long long key = ((unsigned long long)__float_as_uint(d) << 32) | (unsigned)p;
                minkey = u64min(minkey, key);
                bool in = (d <= R2v);
                unsigned mask = __ballot_sync(0xffffffffu, in);
                if (in){
                    int pos = cnt + __popc(mask & ((1u << l) - 1u));
                    if (pos < 256) cbuf[w*256 + pos] = key;
                }
                cnt += __popc(mask);
            }
        }
#pragma unroll
        for (int off = 16; off > 0; off >>= 1)
            minkey = u64min(minkey, __shfl_down_sync(0xffffffffu, minkey, off));
        minkey = __shfl_sync(0xffffffffu, minkey, 0);
        unsigned fill = (unsigned)minkey;

        if (cnt <= 32){
            unsigned v = (l < cnt) ? (unsigned)cbuf[w*256 + l] : fill;
            usel[w*32 + l] = v;
        } else {
            int n = cnt < 256 ? cnt : 256;
            unsigned long long e[8];
#pragma unroll
            for (int qq = 0; qq < 8; qq++){ int p = qq*32 + l; e[qq] = (p < n) ? cbuf[w*256 + p] : ~0ull; }
            for (int r = 0; r < 32; r++){
                unsigned long long loc = ~0ull;
#pragma unroll
                for (int qq = 0; qq < 8; qq++) loc = u64min(loc, e[qq]);
#pragma unroll
                for (int off = 16; off > 0; off >>= 1)
                    loc = u64min(loc, __shfl_down_sync(0xffffffffu, loc, off));
                loc = __shfl_sync(0xffffffffu, loc, 0);
                if (l == r) usel[w*32 + r] = (unsigned)loc;
#pragma unroll
                for (int qq = 0; qq < 8; qq++) if (e[qq] == loc) e[qq] = ~0ull;
            }
        }
        __syncwarp();
        g_bidx[gm*32 + l] = (int)usel[w*32 + l];

        // -------- BN0 stats (needs full g_G for this batch) --------
        __syncthreads();
        if (tid < 64){ ssum[tid] = 0.f; ssq[tid] = 0.f; }
        if (tid == 0){
            while (*((volatile int*)&g_gcnt[b]) < 512) __nanosleep(64);
            __threadfence();
        }
        __syncthreads();

        // center projection (bit-identical to C arithmetic)
        const float* wrA = w0 + l*67;
        const float* wrB = w0 + (32 + l)*67;
        float Cc1 = qx*wrA[0]; Cc1 = fmaf(qy, wrA[1], Cc1); Cc1 = fmaf(qz, wrA[2], Cc1);
        float Cc2 = qx*wrB[0]; Cc2 = fmaf(qy, wrB[1], Cc2); Cc2 = fmaf(qz, wrB[2], Cc2);

        const float* Gb = g_G + (size_t)b*NPTS*64;
        float s1 = 0.f, q1 = 0.f, s2 = 0.f, q2 = 0.f;
        for (int s = 0; s < 32; s++){
            unsigned ip = usel[w*32 + s];
            float ga  = Gb[(size_t)ip*64 + l] - Cc1;
            float gb2 = Gb[(size_t)ip*64 + 32 + l] - Cc2;
            s1 += ga;  q1 = fmaf(ga, ga, q1);
            s2 += gb2; q2 = fmaf(gb2, gb2, q2);
        }
        atomicAdd(&ssum[l], s1);      atomicAdd(&ssq[l], q1);
        atomicAdd(&ssum[32+l], s2);   atomicAdd(&ssq[32+l], q2);
        __syncthreads();
        if (tid < 64){
            int slot = bq & 31;
            atomicAdd(&g_stats[SUM0 + tid*32 + slot], ssum[tid]);
            atomicAdd(&g_stats[SQ0  + tid*32 + slot], ssq[tid]);
        }
    }
}

// ---------------- BN finalize: warp per channel ----------------
__global__ void __launch_bounds__(1024) fin_kernel(
        const float* __restrict__ gamma, const float* __restrict__ beta,
        int sumoff, int sqoff, int aoff, int coff, int nch){
    int w = threadIdx.x >> 5, l = threadIdx.x & 31;
    int c = blockIdx.x*32 + w;
    if (c >= nch) return;
    float s = g_stats[sumoff + c*32 + l];
    float q = g_stats[sqoff  + c*32 + l];
#pragma unroll
    for (int off = 16; off > 0; off >>= 1){
        s += __shfl_down_sync(0xffffffffu, s, off);
        q += __shfl_down_sync(0xffffffffu, q, off);
    }
    if (l == 0){
        const float invN = 1.f / (float)NROWS;
        float mean = s * invN;
        float var = q * invN - mean*mean;
        float rstd = rsqrtf(var + 1e-5f);
        float a = gamma[c] * rstd;
        g_aff[aoff + c] = a;
        g_aff[coff + c] = beta[c] - mean * a;
    }
}

// ---------------- layer1: tf32 MMA, 256 thr, 128 rows x 64 cols ----------------
#define P1 68
__global__ void __launch_bounds__(256) l1_kernel(const float* __restrict__ w1, const float* __restrict__ b1){
    extern __shared__ float smf[];
    uint32_t* xs = (uint32_t*)smf;        // [128][P1] (r, kperm)
    uint32_t* ws = xs + 128*P1;           // [64][P1]  (n, kperm)
    int*   sidx = (int*)(ws + 64*P1);     // 128
    float* ssum = (float*)(sidx + 128);   // 64
    float* ssq  = ssum + 64;              // 64

    int tid = threadIdx.x;
    int w = tid >> 5, lane = tid & 31;
    int g = lane >> 2, tig = lane & 3;
    int wr = w >> 1, wc = w & 1;          // row-tile 0..3, col-tile 0..1
    int m0 = blockIdx.x * 4;
    int b = m0 >> 10;

    if (tid < 64){ ssum[tid] = 0.f; ssq[tid] = 0.f; }
    if (tid < 128) sidx[tid] = g_bidx[m0*32 + tid];
    for (int i = tid; i < 64*64; i += 256){
        int c = i >> 6, k = i & 63;
        ws[c*P1 + kperm(k)] = f2tf32(w1[i]);
    }
    __syncthreads();

    const float* Gb = g_G + (size_t)b*NPTS*64;
#pragma unroll 8
    for (int e = 0; e < 32; e++){
        int flat = e*256 + tid;
        int r = flat >> 6, c = flat & 63;
        int gm = m0 + (r >> 5);
        float y = Gb[(size_t)sidx[r]*64 + c] - g_C[gm*64 + c];
        xs[r*P1 + kperm(c)] = f2tf32(fmaxf(fmaf(g_aff[A0 + c], y, g_aff[C0A + c]), 0.f));
    }
    __syncthreads();

    float4 d[2][4];
#pragma unroll
    for (int mt = 0; mt < 2; mt++)
#pragma unroll
        for (int nt = 0; nt < 4; nt++) d[mt][nt] = make_float4(0.f,0.f,0.f,0.f);

    int xbase = (wr*32 + g)*P1;
    int wbase = (wc*32 + g)*P1;
#pragma unroll
    for (int kt = 0; kt < 8; kt++){
        int ko = kt*8 + 2*tig;
        uint32_t a[2][4];
#pragma unroll
        for (int mt = 0; mt < 2; mt++){
            int ro = xbase + mt*16*P1;
            uint2 a02 = *(const uint2*)&xs[ro + ko];
            uint2 a13 = *(const uint2*)&xs[ro + 8*P1 + ko];
            a[mt][0] = a02.x; a[mt][2] = a02.y;
            a[mt][1] = a13.x; a[mt][3] = a13.y;
        }
        uint32_t bf[4][2];
#pragma unroll
        for (int nt = 0; nt < 4; nt++){
            uint2 bv = *(const uint2*)&ws[wbase + nt*8*P1 + ko];
            bf[nt][0] = bv.x; bf[nt][1] = bv.y;
        }
#pragma unroll
        for (int nt = 0; nt < 4; nt++)
#pragma unroll
            for (int mt = 0; mt < 2; mt++)
                mma_tf32(d[mt][nt], a[mt], bf[nt]);
    }

    // epilogue: bias, store Y1, stats
#pragma unroll
    for (int nt = 0; nt < 4; nt++){
        int c0 = wc*32 + nt*8 + 2*tig;
        float bb0 = b1[c0], bb1 = b1[c0+1];
        float s0 = 0.f, s1v = 0.f, q0 = 0.f, q1v = 0.f;
#pragma unroll
        for (int mt = 0; mt < 2; mt++){
            size_t R = (size_t)m0*32 + wr*32 + mt*16 + g;
            float y00 = d[mt][nt].x + bb0, y01 = d[mt][nt].y + bb1;
            float y10 = d[mt][nt].z + bb0, y11 = d[mt][nt].w + bb1;
            *(float2*)&g_Y1[R*64 + c0]     = make_float2(y00, y01);
            *(float2*)&g_Y1[(R+8)*64 + c0] = make_float2(y10, y11);
            s0 += y00 + y10; s1v += y01 + y11;
            q0 += y00*y00 + y10*y10; q1v += y01*y01 + y11*y11;
        }
#pragma unroll
        for (int off = 16; off >= 4; off >>= 1){
            s0  += __shfl_down_sync(0xffffffffu, s0,  off);
            s1v += __shfl_down_sync(0xffffffffu, s1v, off);
            q0  += __shfl_down_sync(0xffffffffu, q0,  off);
            q1v += __shfl_down_sync(0xffffffffu, q1v, off);
        }
        if (g == 0){
            atomicAdd(&ssum[c0], s0);   atomicAdd(&ssum[c0+1], s1v);
            atomicAdd(&ssq[c0],  q0);   atomicAdd(&ssq[c0+1],  q1v);
        }
    }
    __syncthreads();
    if (tid < 64){
        int slot = blockIdx.x & 31;
        atomicAdd(&g_stats[SUM1 + tid*32 + slot], ssum[tid]);
        atomicAdd(&g_stats[SQ1  + tid*32 + slot], ssq[tid]);
    }
}

// ---------------- layer2: tf32 MMA, 256 thr, 64 rows x 128 cols, fused pool ----------------
#define P2 68
__global__ void __launch_bounds__(256) l2_kernel(const float* __restrict__ w2, const float* __restrict__ b2){
    extern __shared__ float smf[];
    uint32_t* xs  = (uint32_t*)smf;        // [64][P2]  (r, kperm)
    uint32_t* ws  = xs + 64*P2;            // [128][P2] (n, kperm)
    float* ssum = (float*)(ws + 128*P2);   // 128
    float* ssq  = ssum + 128;              // 128

    int tid = threadIdx.x;
    int w = tid >> 5, lane = tid & 31;
    int g = lane >> 2, tig = lane & 3;
    int wr = w >> 2, wc = w & 3;           // row-tile 0..1 (one center each), col-tile 0..3
    int m0 = blockIdx.x * 2;

    if (tid < 128){ ssum[tid] = 0.f; ssq[tid] = 0.f; }
    for (int i = tid; i < 128*64; i += 256){
        int c = i >> 6, k = i & 63;
        ws[c*P2 + kperm(k)] = f2tf32(w2[i]);
    }
    for (int i = tid; i < 64*64; i += 256){
        int r = i >> 6, k = i & 63;
        float y = g_Y1[((size_t)m0*32 + r)*64 + k];
        xs[r*P2 + kperm(k)] = f2tf32(fmaxf(fmaf(g_aff[A1 + k], y, g_aff[C1A + k]), 0.f));
    }
    __syncthreads();

    float4 d[2][4];
#pragma unroll
    for (int mt = 0; mt < 2; mt++)
#pragma unroll
        for (int nt = 0; nt < 4; nt++) d[mt][nt] = make_float4(0.f,0.f,0.f,0.f);

    int xbase = (wr*32 + g)*P2;
    int wbase = (wc*32 + g)*P2;
#pragma unroll
    for (int kt = 0; kt < 8; kt++){
        int ko = kt*8 + 2*tig;
        uint32_t a[2][4];
#pragma unroll
        for (int mt = 0; mt < 2; mt++){
            int ro = xbase + mt*16*P2;
            uint2 a02 = *(const uint2*)&xs[ro + ko];
            uint2 a13 = *(const uint2*)&xs[ro + 8*P2 + ko];
            a[mt][0] = a02.x; a[mt][2] = a02.y;
            a[mt][1] = a13.x; a[mt][3] = a13.y;
        }
        uint32_t bf[4][2];
#pragma unroll
        for (int nt = 0; nt < 4; nt++){
            uint2 bv = *(const uint2*)&ws[wbase + nt*8*P2 + ko];
            bf[nt][0] = bv.x; bf[nt][1] = bv.y;
        }
#pragma unroll
        for (int nt = 0; nt < 4; nt++)
#pragma unroll
            for (int mt = 0; mt < 2; mt++)
                mma_tf32(d[mt][nt], a[mt], bf[nt]);
    }

    // epilogue: bias, pool over center rows (within warp), stats
    int cent = m0 + wr;
#pragma unroll
    for (int nt = 0; nt < 4; nt++){
        int c0 = wc*32 + nt*8 + 2*tig;
        float bb0 = b2[c0], bb1 = b2[c0+1];
        float y00a = d[0][nt].x + bb0, y01a = d[0][nt].y + bb1;
        float y10a = d[0][nt].z + bb0, y11a = d[0][nt].w + bb1;
        float y00b = d[1][nt].x + bb0, y01b = d[1][nt].y + bb1;
        float y10b = d[1][nt].z + bb0, y11b = d[1][nt].w + bb1;
        float mx0 = fmaxf(fmaxf(y00a, y10a), fmaxf(y00b, y10b));
        float mx1 = fmaxf(fmaxf(y01a, y11a), fmaxf(y01b, y11b));
        float mn0 = fminf(fminf(y00a, y10a), fminf(y00b, y10b));
        float mn1 = fminf(fminf(y01a, y11a), fminf(y01b, y11b));
        float s0 = y00a + y10a + y00b + y10b;
        float s1v = y01a + y11a + y01b + y11b;
        float q0 = y00a*y00a + y10a*y10a + y00b*y00b + y10b*y10b;
        float q1v = y01a*y01a + y11a*y11a + y01b*y01b + y11b*y11b;
#pragma unroll
        for (int off = 16; off >= 4; off >>= 1){
            mx0 = fmaxf(mx0, __shfl_down_sync(0xffffffffu, mx0, off));
            mx1 = fmaxf(mx1, __shfl_down_sync(0xffffffffu, mx1, off));
            mn0 = fminf(mn0, __shfl_down_sync(0xffffffffu, mn0, off));
            mn1 = fminf(mn1, __shfl_down_sync(0xffffffffu, mn1, off));
            s0  += __shfl_down_sync(0xffffffffu, s0,  off);
            s1v += __shfl_down_sync(0xffffffffu, s1v, off);
            q0  += __shfl_down_sync(0xffffffffu, q0,  off);
            q1v += __shfl_down_sync(0xffffffffu, q1v, off);
        }
        if (g == 0){
            g_mx[(size_t)cent*128 + c0]   = mx0;
            g_mx[(size_t)cent*128 + c0+1] = mx1;
            g_mn[(size_t)cent*128 + c0]   = mn0;
            g_mn[(size_t)cent*128 + c0+1] = mn1;
            atomicAdd(&ssum[c0], s0);   atomicAdd(&ssum[c0+1], s1v);
            atomicAdd(&ssq[c0],  q0);   atomicAdd(&ssq[c0+1],  q1v);
        }
    }
    __syncthreads();
    if (tid < 128){
        int slot = blockIdx.x & 31;
        atomicAdd(&g_stats[SUM2 + tid*32 + slot], ssum[tid]);
        atomicAdd(&g_stats[SQ2  + tid*32 + slot], ssq[tid]);
    }
}

// ---------------- final: BN2+ReLU on pooled extremum ----------------
__global__ void out_kernel(float* __restrict__ out){
    int i = blockIdx.x*256 + threadIdx.x;   // NCTR_TOT*128
    int c = i & 127;
    float a = g_aff[A2 + c];
    float v = (a >= 0.f) ? g_mx[i] : g_mn[i];
    out[OUT_XYZ_ELEMS + i] = fmaxf(fmaf(a, v, g_aff[C2A + c]), 0.f);
}

// ---------------- host launcher ----------------
extern "C" void kernel_launch(void* const* d_in, const int* in_sizes, int n_in,
                              void* d_out, int out_size){
    const float* xyz   = (const float*)d_in[0];
    const float* feat  = (const float*)d_in[1];
    const float* w0 = (const float*)d_in[2];
    const float* b0 = (const float*)d_in[3];
    const float* g0 = (const float*)d_in[4];
    const float* be0 = (const float*)d_in[5];
    const float* w1 = (const float*)d_in[6];
    const float* b1 = (const float*)d_in[7];
    const float* g1 = (const float*)d_in[8];
    const float* be1 = (const float*)d_in[9];
    const float* w2 = (const float*)d_in[10];
    const float* b2 = (const float*)d_in[11];
    const float* g2 = (const float*)d_in[12];
    const float* be2 = (const float*)d_in[13];
    float* out = (float*)d_out;

    static const int MEGA_SMEM = (12288 + 64) * 4;                      // ~49.4 KB
    static const int L1_SMEM  = (128*P1 + 64*P1)*4 + 128*4 + 128*4;     // ~53.2 KB
    static const int L2_SMEM  = (64*P2 + 128*P2)*4 + 256*4;             // ~53.2 KB
    cudaFuncSetAttribute(mega_kernel, cudaFuncAttributeMaxDynamicSharedMemorySize, MEGA_SMEM);
    cudaFuncSetAttribute(l1_kernel,  cudaFuncAttributeMaxDynamicSharedMemorySize, L1_SMEM);
    cudaFuncSetAttribute(l2_kernel,  cudaFuncAttributeMaxDynamicSharedMemorySize, L2_SMEM);

    mega_kernel<<<FPS_NB + G_NB + BQ_NB, 512, MEGA_SMEM>>>(xyz, feat, w0, b0, out);
    fin_kernel<<<2, 1024>>>(g0, be0, SUM0, SQ0, A0, C0A, 64);
    l1_kernel<<<NCTR_TOT/4, 256, L1_SMEM>>>(w1, b1);
    fin_kernel<<<2, 1024>>>(g1, be1, SUM1, SQ1, A1, C1A, 64);
    l2_kernel<<<NCTR_TOT/2, 256, L2_SMEM>>>(w2, b2);
    fin_kernel<<<4, 1024>>>(g2, be2, SUM2, SQ2, A2, C2A, 128);
    out_kernel<<<NCTR_TOT*128/256, 256>>>(out);
}

// round 11
// speedup vs baseline: 1.5324x; 1.5324x over previous
#include <cuda_runtime.h>
#include <cuda_bf16.h>
#include <math.h>
#include <stdint.h>

// ---------------- problem constants ----------------
#define BATCH 16
#define NPTS 4096
#define NCTR 1024
#define NSAMP 32
#define NROWS (BATCH*NCTR*NSAMP)          // 524288
#define NCTR_TOT (BATCH*NCTR)             // 16384
#define OUT_XYZ_ELEMS (NCTR_TOT*3)        // 49152
#define FPS_NB 16
#define G_NB (BATCH*NPTS/4)               // 16384
#define BQ_NB (NCTR_TOT/8)                // 2048

// stats layout (32 slots per channel, sum then sq)
#define SUM0 0
#define SQ0  (64*32)
#define SUM1 (2*64*32)
#define SQ1  (3*64*32)
#define SUM2 (4*64*32)
#define SQ2  (4*64*32 + 128*32)
#define STATS_TOT (4*64*32 + 2*128*32)    // 16384

// affine layout
#define A0 0
#define C0A 64
#define A1 128
#define C1A 192
#define A2 256
#define C2A 384

// ---------------- scratch (static device memory; no allocs) ----------------
__device__ int   g_fps[NCTR_TOT];
__device__ int   g_bidx[NROWS];
__device__ float g_G[BATCH*NPTS*64];      // 16 MB
__device__ float g_C[NCTR_TOT*64];        // 4 MB
__device__ float g_Y1[NROWS*64];          // 134 MB
__device__ float g_mx[NCTR_TOT*128];      // 8 MB
__device__ float g_mn[NCTR_TOT*128];      // 8 MB
__device__ float g_stats[STATS_TOT];
__device__ float g_aff[512];
__device__ volatile int g_prog[BATCH];    // FPS progress (monotone across replays)
__device__ int g_gcnt[BATCH];             // G-completion counter (monotone)

__device__ __forceinline__ unsigned long long u64min(unsigned long long a, unsigned long long b){
    return a < b ? a : b;
}
__device__ __forceinline__ uint32_t f2tf32(float x){
    uint32_t r; asm("cvt.rna.tf32.f32 %0, %1;" : "=r"(r) : "f"(x)); return r;
}
__device__ __forceinline__ void mma_tf32(float4& d, const uint32_t* a, const uint32_t* b){
    asm volatile("mma.sync.aligned.m16n8k8.row.col.f32.tf32.tf32.f32 "
                 "{%0,%1,%2,%3},{%4,%5,%6,%7},{%8,%9},{%0,%1,%2,%3};"
                 : "+f"(d.x),"+f"(d.y),"+f"(d.z),"+f"(d.w)
                 : "r"(a[0]),"r"(a[1]),"r"(a[2]),"r"(a[3]),"r"(b[0]),"r"(b[1]));
}
// packed f32x2 helpers
__device__ __forceinline__ unsigned long long pk2(float lo, float hi){
    unsigned long long r; asm("mov.b64 %0,{%1,%2};" : "=l"(r) : "f"(lo), "f"(hi)); return r;
}
__device__ __forceinline__ void unpk2(unsigned long long v, float& lo, float& hi){
    asm("mov.b64 {%0,%1},%2;" : "=f"(lo), "=f"(hi) : "l"(v));
}
__device__ __forceinline__ unsigned long long add2(unsigned long long a, unsigned long long b){
    unsigned long long r; asm("add.rn.f32x2 %0,%1,%2;" : "=l"(r) : "l"(a), "l"(b)); return r;
}
__device__ __forceinline__ unsigned long long mul2(unsigned long long a, unsigned long long b){
    unsigned long long r; asm("mul.rn.f32x2 %0,%1,%2;" : "=l"(r) : "l"(a), "l"(b)); return r;
}
__device__ __forceinline__ unsigned long long fma2(unsigned long long a, unsigned long long b, unsigned long long c){
    unsigned long long r; asm("fma.rn.f32x2 %0,%1,%2,%3;" : "=l"(r) : "l"(a), "l"(b), "l"(c)); return r;
}
// k-pair permutation: within each group of 8 k's, place (k, k+4) adjacently
__device__ __forceinline__ int kperm(int k){
    return (k & ~7) | ((k & 3) << 1) | ((k >> 2) & 1);
}

// =====================================================================
// MEGA (256 thr): [0,16) FPS | [16,16+16384) G | rest: ballq+BN0 stats
// =====================================================================
__global__ void __launch_bounds__(256) mega_kernel(
        const float* __restrict__ xyz, const float* __restrict__ feat,
        const float* __restrict__ w0, const float* __restrict__ b0,
        float* __restrict__ out){
    extern __shared__ float sm[];
    int tid = threadIdx.x;
    int bx = blockIdx.x;

    if (bx < FPS_NB){
        // ---------------- FPS: 256 thr, 16 pts/thread ----------------
        float* sx = sm;               // 4096
        float* sy = sm + 4096;
        float* sz = sm + 8192;
        float (*srd)[8] = (float(*)[8])(sm + 12288);   // [2][8]
        int*   s_idx    = (int*)(sm + 12288 + 16);     // [2]

        int b = bx;
        const float* xb = xyz + (size_t)b*NPTS*3;

        float px[16], py[16], pz[16], dist[16];
#pragma unroll
        for (int k = 0; k < 16; k++){
            int p = k*256 + tid;
            float x = xb[p*3], y = xb[p*3+1], z = xb[p*3+2];
            px[k]=x; py[k]=y; pz[k]=z; dist[k]=INFINITY;
            sx[p]=x; sy[p]=y; sz[p]=z;
        }
        unsigned long long px2[8], py2[8], pz2[8];
#pragma unroll
        for (int j = 0; j < 8; j++){
            px2[j] = pk2(px[2*j], px[2*j+1]);
            py2[j] = pk2(py[2*j], py[2*j+1]);
            pz2[j] = pk2(pz[2*j], pz[2*j+1]);
        }
        if (tid == 0){ g_fps[b*NCTR] = 0; s_idx[0] = 0x7fffffff; s_idx[1] = 0x7fffffff; }
        float cx = xb[0], cy = xb[1], cz = xb[2];
        __syncthreads();

        int w = tid >> 5;
        for (int t = 1; t < NCTR; t++){
            unsigned long long ncx = pk2(-cx,-cx), ncy = pk2(-cy,-cy), ncz = pk2(-cz,-cz);
            float m = -1.f;
#pragma unroll
            for (int j = 0; j < 8; j++){
                unsigned long long dx = add2(px2[j], ncx);
                unsigned long long dy = add2(py2[j], ncy);
                unsigned long long dz = add2(pz2[j], ncz);
                unsigned long long dd = fma2(dx, dx, fma2(dy, dy, mul2(dz, dz)));
                float dlo, dhi; unpk2(dd, dlo, dhi);
                dist[2*j]   = fminf(dist[2*j],   dlo);
                dist[2*j+1] = fminf(dist[2*j+1], dhi);
                m = fmaxf(m, fmaxf(dist[2*j], dist[2*j+1]));
            }
            // warp max (value only)
            float wm = m;
#pragma unroll
            for (int off = 16; off > 0; off >>= 1)
                wm = fmaxf(wm, __shfl_down_sync(0xffffffffu, wm, off));
            int pb = t & 1;
            if ((tid & 31) == 0) srd[pb][w] = wm;
            __syncthreads();
            float bm = srd[pb][0];
#pragma unroll
            for (int ww = 1; ww < 8; ww++) bm = fmaxf(bm, srd[pb][ww]);
            if (tid == 0) s_idx[1 - pb] = 0x7fffffff;   // reset other buffer
            if (m == bm){
                int cand = 0x7fffffff;
#pragma unroll
                for (int k = 15; k >= 0; k--)
                    if (dist[k] == bm) cand = k*256 + tid;
                atomicMin(&s_idx[pb], cand);
            }
            __syncthreads();
            int bi2 = s_idx[pb];
            cx = sx[bi2]; cy = sy[bi2]; cz = sz[bi2];
            if (tid == 0){
                g_fps[b*NCTR + t] = bi2;
                if ((t & 31) == 31){ __threadfence(); g_prog[b] = t; }
            }
        }
        __syncthreads();

        // new_xyz gather
        for (int i = tid; i < NCTR; i += 256){
            int idx = g_fps[b*NCTR + i];
            size_t o = (size_t)(b*NCTR + i)*3;
            out[o+0] = sx[idx]; out[o+1] = sy[idx]; out[o+2] = sz[idx];
        }
        __syncthreads();

        // C = new_xyz @ W0xT  (used by l1)
        for (int i = tid; i < NCTR*64; i += 256){
            int m2 = i >> 6, c = i & 63;
            const float* wr = w0 + c*67;
            size_t o = (size_t)(b*NCTR + m2)*3;
            float acc = out[o+0]*wr[0];
            acc = fmaf(out[o+1], wr[1], acc);
            acc = fmaf(out[o+2], wr[2], acc);
            g_C[(size_t)(b*NCTR + m2)*64 + c] = acc;
        }
    } else if (bx < FPS_NB + G_NB){
        // ---------------- G branch: 4 points per block ----------------
        int gb = bx - FPS_NB;
        if (gb < 16){
            for (int i = gb*1024 + tid; i < (gb+1)*1024; i += 256) g_stats[i] = 0.f;
        }
        float* w0s = sm;   // 64*67 floats
        for (int i = tid; i < 64*67; i += 256) w0s[i] = w0[i];
        __syncthreads();
        int p = gb*4 + (tid >> 6);
        int c = tid & 63;
        const float* fr = feat + (size_t)p*64;
        const float* wr = w0s + c*67;
        float acc = b0[c];
        acc = fmaf(xyz[p*3+0], wr[0], acc);
        acc = fmaf(xyz[p*3+1], wr[1], acc);
        acc = fmaf(xyz[p*3+2], wr[2], acc);
#pragma unroll 8
        for (int k = 0; k < 64; k++) acc = fmaf(fr[k], wr[3+k], acc);
        g_G[(size_t)p*64 + c] = acc;
        __syncthreads();
        if (tid == 0){
            __threadfence();
            atomicAdd(&g_gcnt[gb >> 10], 1);
        }
    } else {
        // ---------------- ball query + BN0 stats (polls FPS/G progress) ----------------
        float* sxq = sm;                                      // 1024
        float* syq = sm + 1024;
        float* szq = sm + 2048;
        unsigned long long* cbuf = (unsigned long long*)(sm + 3072);  // [8][256]
        unsigned* usel = (unsigned*)(sm + 7168);              // [8][32]
        float* ssum = sm + 7424;                              // 64
        float* ssq  = sm + 7488;                              // 64

        int bq = bx - (FPS_NB + G_NB);
        int b = bq >> 7;
        int q = bq & 127;
        int w = tid >> 5, l = tid & 31;
        int m = q*8 + w;
        int gm = b*NCTR + m;

        if (tid == 0){
            int need = q*8 + 7;
            while (g_prog[b] < need) __nanosleep(128);
            __threadfence();
        }
        __syncthreads();

        int cidx = g_fps[gm];
        const float* xb = xyz + (size_t)b*NPTS*3;
        float qx = xb[cidx*3], qy = xb[cidx*3+1], qz = xb[cidx*3+2];
        const float R2v = (float)(0.2*0.2);

        unsigned long long minkey = ~0ull;
        int cnt = 0;

        for (int ch = 0; ch < 4; ch++){
            __syncthreads();
            for (int i = tid; i < 1024; i += 256){
                int p = ch*1024 + i;
                sxq[i] = xb[p*3]; syq[i] = xb[p*3+1]; szq[i] = xb[p*3+2];
            }
            __syncthreads();
            for (int j = 0; j < 32; j++){
                int pl = j*32 + l;
                float dx = qx - sxq[pl], dy = qy - syq[pl], dz = qz - szq[pl];
                float d = fmaf(dx,dx, fmaf(dy,dy, dz*dz));
                int p = ch*1024 + pl;
                unsigned long long key = ((unsigned long long)__float_as_uint(d) << 32) | (unsigned)p;
                minkey = u64min(minkey, key);
                bool in = (d <= R2v);
                unsigned mask = __ballot_sync(0xffffffffu, in);
                if (in){
                    int pos = cnt + __popc(mask & ((1u << l) - 1u));
                    if (pos < 256) cbuf[w*256 + pos] = key;
                }
                cnt += __popc(mask);
            }
        }
#pragma unroll
        for (int off = 16; off > 0; off >>= 1)
            minkey = u64min(minkey, __shfl_down_sync(0xffffffffu, minkey, off));
        minkey = __shfl_sync(0xffffffffu, minkey, 0);
        unsigned fill = (unsigned)minkey;

        if (cnt <= 32){
            unsigned v = (l < cnt) ? (unsigned)cbuf[w*256 + l] : fill;
            usel[w*32 + l] = v;
        } else {
            int n = cnt < 256 ? cnt : 256;
            unsigned long long e[8];
#pragma unroll
            for (int qq = 0; qq < 8; qq++){ int p = qq*32 + l; e[qq] = (p < n) ? cbuf[w*256 + p] : ~0ull; }
            for (int r = 0; r < 32; r++){
                unsigned long long loc = ~0ull;
#pragma unroll
                for (int qq = 0; qq < 8; qq++) loc = u64min(loc, e[qq]);
#pragma unroll
                for (int off = 16; off > 0; off >>= 1)
                    loc = u64min(loc, __shfl_down_sync(0xffffffffu, loc, off));
                loc = __shfl_sync(0xffffffffu, loc, 0);
                if (l == r) usel[w*32 + r] = (unsigned)loc;
#pragma unroll
                for (int qq = 0; qq < 8; qq++) if (e[qq] == loc) e[qq] = ~0ull;
            }
        }
        __syncwarp();
        g_bidx[gm*32 + l] = (int)usel[w*32 + l];

        // -------- BN0 stats (needs full g_G for this batch) --------
        __syncthreads();
        if (tid < 64){ ssum[tid] = 0.f; ssq[tid] = 0.f; }
        if (tid == 0){
            while (*((volatile int*)&g_gcnt[b]) < 1024) __nanosleep(64);
            __threadfence();
        }
        __syncthreads();

        // center projection (bit-identical to C arithmetic)
        const float* wrA = w0 + l*67;
        const float* wrB = w0 + (32 + l)*67;
        float Cc1 = qx*wrA[0]; Cc1 = fmaf(qy, wrA[1], Cc1); Cc1 = fmaf(qz, wrA[2], Cc1);
        float Cc2 = qx*wrB[0]; Cc2 = fmaf(qy, wrB[1], Cc2); Cc2 = fmaf(qz, wrB[2], Cc2);

        const float* Gb = g_G + (size_t)b*NPTS*64;
        float s1 = 0.f, q1 = 0.f, s2 = 0.f, q2 = 0.f;
        for (int s = 0; s < 32; s++){
            unsigned ip = usel[w*32 + s];
            float ga  = Gb[(size_t)ip*64 + l] - Cc1;
            float gb2 = Gb[(size_t)ip*64 + 32 + l] - Cc2;
            s1 += ga;  q1 = fmaf(ga, ga, q1);
            s2 += gb2; q2 = fmaf(gb2, gb2, q2);
        }
        atomicAdd(&ssum[l], s1);      atomicAdd(&ssq[l], q1);
        atomicAdd(&ssum[32+l], s2);   atomicAdd(&ssq[32+l], q2);
        __syncthreads();
        if (tid < 64){
            int slot = bq & 31;
            atomicAdd(&g_stats[SUM0 + tid*32 + slot], ssum[tid]);
            atomicAdd(&g_stats[SQ0  + tid*32 + slot], ssq[tid]);
        }
    }
}

// ---------------- BN finalize: warp per channel ----------------
__global__ void __launch_bounds__(1024) fin_kernel(
        const float* __restrict__ gamma, const float* __restrict__ beta,
        int sumoff, int sqoff, int aoff, int coff, int nch){
    int w = threadIdx.x >> 5, l = threadIdx.x & 31;
    int c = blockIdx.x*32 + w;
    if (c >= nch) return;
    float s = g_stats[sumoff + c*32 + l];
    float q = g_stats[sqoff  + c*32 + l];
#pragma unroll
    for (int off = 16; off > 0; off >>= 1){
        s += __shfl_down_sync(0xffffffffu, s, off);
        q += __shfl_down_sync(0xffffffffu, q, off);
    }
    if (l == 0){
        const float invN = 1.f / (float)NROWS;
        float mean = s * invN;
        float var = q * invN - mean*mean;
        float rstd = rsqrtf(var + 1e-5f);
        float a = gamma[c] * rstd;
        g_aff[aoff + c] = a;
        g_aff[coff + c] = beta[c] - mean * a;
    }
}

// ---------------- layer1: tf32 MMA, 256 thr, 128 rows x 64 cols ----------------
#define P1 68
__global__ void __launch_bounds__(256) l1_kernel(const float* __restrict__ w1, const float* __restrict__ b1){
    extern __shared__ float smf[];
    uint32_t* xs = (uint32_t*)smf;        // [128][P1] (r, kperm)
    uint32_t* ws = xs + 128*P1;           // [64][P1]  (n, kperm)
    int*   sidx = (int*)(ws + 64*P1);     // 128
    float* ssum = (float*)(sidx + 128);   // 64
    float* ssq  = ssum + 64;              // 64

    int tid = threadIdx.x;
    int w = tid >> 5, lane = tid & 31;
    int g = lane >> 2, tig = lane & 3;
    int wr = w >> 1, wc = w & 1;          // row-tile 0..3, col-tile 0..1
    int m0 = blockIdx.x * 4;
    int b = m0 >> 10;

    if (tid < 64){ ssum[tid] = 0.f; ssq[tid] = 0.f; }
    if (tid < 128) sidx[tid] = g_bidx[m0*32 + tid];
    // weights: float4 loads, kperm scatter
#pragma unroll
    for (int it = 0; it < 4; it++){
        int i = it*256 + tid;             // 1024 float4 total
        int c = i >> 4, k0 = (i & 15)*4;
        float4 v = *(const float4*)&w1[c*64 + k0];
        ws[c*P1 + kperm(k0+0)] = f2tf32(v.x);
        ws[c*P1 + kperm(k0+1)] = f2tf32(v.y);
        ws[c*P1 + kperm(k0+2)] = f2tf32(v.z);
        ws[c*P1 + kperm(k0+3)] = f2tf32(v.w);
    }
    __syncthreads();

    const float* Gb = g_G + (size_t)b*NPTS*64;
#pragma unroll
    for (int it = 0; it < 8; it++){
        int i = it*256 + tid;             // 2048 float4 total
        int r = i >> 4, c0 = (i & 15)*4;
        int gm = m0 + (r >> 5);
        float4 gv = *(const float4*)&Gb[(size_t)sidx[r]*64 + c0];
        float4 cv = *(const float4*)&g_C[(size_t)gm*64 + c0];
        xs[r*P1 + kperm(c0+0)] = f2tf32(fmaxf(fmaf(g_aff[A0 + c0+0], gv.x - cv.x, g_aff[C0A + c0+0]), 0.f));
        xs[r*P1 + kperm(c0+1)] = f2tf32(fmaxf(fmaf(g_aff[A0 + c0+1], gv.y - cv.y, g_aff[C0A + c0+1]), 0.f));
        xs[r*P1 + kperm(c0+2)] = f2tf32(fmaxf(fmaf(g_aff[A0 + c0+2], gv.z - cv.z, g_aff[C0A + c0+2]), 0.f));
        xs[r*P1 + kperm(c0+3)] = f2tf32(fmaxf(fmaf(g_aff[A0 + c0+3], gv.w - cv.w, g_aff[C0A + c0+3]), 0.f));
    }
    __syncthreads();

    float4 d[2][4];
#pragma unroll
    for (int mt = 0; mt < 2; mt++)
#pragma unroll
        for (int nt = 0; nt < 4; nt++) d[mt][nt] = make_float4(0.f,0.f,0.f,0.f);

    int xbase = (wr*32 + g)*P1;
    int wbase = (wc*32 + g)*P1;
#pragma unroll
    for (int kt = 0; kt < 8; kt++){
        int ko = kt*8 + 2*tig;
        uint32_t a[2][4];
#pragma unroll
        for (int mt = 0; mt < 2; mt++){
            int ro = xbase + mt*16*P1;
            uint2 a02 = *(const uint2*)&xs[ro + ko];
            uint2 a13 = *(const uint2*)&xs[ro + 8*P1 + ko];
            a[mt][0] = a02.x; a[mt][2] = a02.y;
            a[mt][1] = a13.x; a[mt][3] = a13.y;
        }
        uint32_t bf[4][2];
#pragma unroll
        for (int nt = 0; nt < 4; nt++){
            uint2 bv = *(const uint2*)&ws[wbase + nt*8*P1 + ko];
            bf[nt][0] = bv.x; bf[nt][1] = bv.y;
        }
#pragma unroll
        for (int nt = 0; nt < 4; nt++)
#pragma unroll
            for (int mt = 0; mt < 2; mt++)
                mma_tf32(d[mt][nt], a[mt], bf[nt]);
    }

    // epilogue: bias, store Y1, stats
#pragma unroll
    for (int nt = 0; nt < 4; nt++){
        int c0 = wc*32 + nt*8 + 2*tig;
        float bb0 = b1[c0], bb1 = b1[c0+1];
        float s0 = 0.f, s1v = 0.f, q0 = 0.f, q1v = 0.f;
#pragma unroll
        for (int mt = 0; mt < 2; mt++){
            size_t R = (size_t)m0*32 + wr*32 + mt*16 + g;
            float y00 = d[mt][nt].x + bb0, y01 = d[mt][nt].y + bb1;
            float y10 = d[mt][nt].z + bb0, y11 = d[mt][nt].w + bb1;
            *(float2*)&g_Y1[R*64 + c0]     = make_float2(y00, y01);
            *(float2*)&g_Y1[(R+8)*64 + c0] = make_float2(y10, y11);
            s0 += y00 + y10; s1v += y01 + y11;
            q0 += y00*y00 + y10*y10; q1v += y01*y01 + y11*y11;
        }
#pragma unroll
        for (int off = 16; off >= 4; off >>= 1){
            s0  += __shfl_down_sync(0xffffffffu, s0,  off);
            s1v += __shfl_down_sync(0xffffffffu, s1v, off);
            q0  += __shfl_down_sync(0xffffffffu, q0,  off);
            q1v += __shfl_down_sync(0xffffffffu, q1v, off);
        }
        if (g == 0){
            atomicAdd(&ssum[c0], s0);   atomicAdd(&ssum[c0+1], s1v);
            atomicAdd(&ssq[c0],  q0);   atomicAdd(&ssq[c0+1],  q1v);
        }
    }
    __syncthreads();
    if (tid < 64){
        int slot = blockIdx.x & 31;
        atomicAdd(&g_stats[SUM1 + tid*32 + slot], ssum[tid]);
        atomicAdd(&g_stats[SQ1  + tid*32 + slot], ssq[tid]);
    }
}

// ---------------- layer2: tf32 MMA, 256 thr, 64 rows x 128 cols, fused pool ----------------
#define P2 68
__global__ void __launch_bounds__(256) l2_kernel(const float* __restrict__ w2, const float* __restrict__ b2){
    extern __shared__ float smf[];
    uint32_t* xs  = (uint32_t*)smf;        // [64][P2]  (r, kperm)
    uint32_t* ws  = xs + 64*P2;            // [128][P2] (n, kperm)
    float* ssum = (float*)(ws + 128*P2);   // 128
    float* ssq  = ssum + 128;              // 128

    int tid = threadIdx.x;
    int w = tid >> 5, lane = tid & 31;
    int g = lane >> 2, tig = lane & 3;
    int wr = w >> 2, wc = w & 3;           // row-tile 0..1 (one center each), col-tile 0..3
    int m0 = blockIdx.x * 2;

    if (tid < 128){ ssum[tid] = 0.f; ssq[tid] = 0.f; }
    // weights: float4 loads, kperm scatter (128*64 floats = 2048 float4)
#pragma unroll
    for (int it = 0; it < 8; it++){
        int i = it*256 + tid;
        int c = i >> 4, k0 = (i & 15)*4;
        float4 v = *(const float4*)&w2[c*64 + k0];
        ws[c*P2 + kperm(k0+0)] = f2tf32(v.x);
        ws[c*P2 + kperm(k0+1)] = f2tf32(v.y);
        ws[c*P2 + kperm(k0+2)] = f2tf32(v.z);
        ws[c*P2 + kperm(k0+3)] = f2tf32(v.w);
    }
    // x: float4 loads of Y1 (64*64 = 1024 float4)
    const float* Yb = g_Y1 + (size_t)m0*32*64;
#pragma unroll
    for (int it = 0; it < 4; it++){
        int i = it*256 + tid;
        int r = i >> 4, k0 = (i & 15)*4;
        float4 yv = *(const float4*)&Yb[(size_t)r*64 + k0];
        xs[r*P2 + kperm(k0+0)] = f2tf32(fmaxf(fmaf(g_aff[A1 + k0+0], yv.x, g_aff[C1A + k0+0]), 0.f));
        xs[r*P2 + kperm(k0+1)] = f2tf32(fmaxf(fmaf(g_aff[A1 + k0+1], yv.y, g_aff[C1A + k0+1]), 0.f));
        xs[r*P2 + kperm(k0+2)] = f2tf32(fmaxf(fmaf(g_aff[A1 + k0+2], yv.z, g_aff[C1A + k0+2]), 0.f));
        xs[r*P2 + kperm(k0+3)] = f2tf32(fmaxf(fmaf(g_aff[A1 + k0+3], yv.w, g_aff[C1A + k0+3]), 0.f));
    }
    __syncthreads();

    float4 d[2][4];
#pragma unroll
    for (int mt = 0; mt < 2; mt++)
#pragma unroll
        for (int nt = 0; nt < 4; nt++) d[mt][nt] = make_float4(0.f,0.f,0.f,0.f);

    int xbase = (wr*32 + g)*P2;
    int wbase = (wc*32 + g)*P2;
#pragma unroll
    for (int kt = 0; kt < 8; kt++){
        int ko = kt*8 + 2*tig;
        uint32_t a[2][4];
#pragma unroll
        for (int mt = 0; mt < 2; mt++){
            int ro = xbase + mt*16*P2;
            uint2 a02 = *(const uint2*)&xs[ro + ko];
            uint2 a13 = *(const uint2*)&xs[ro + 8*P2 + ko];
            a[mt][0] = a02.x; a[mt][2] = a02.y;
            a[mt][1] = a13.x; a[mt][3] = a13.y;
        }
        uint32_t bf[4][2];
#pragma unroll
        for (int nt = 0; nt < 4; nt++){
            uint2 bv = *(const uint2*)&ws[wbase + nt*8*P2 + ko];
            bf[nt][0] = bv.x; bf[nt][1] = bv.y;
        }
#pragma unroll
        for (int nt = 0; nt < 4; nt++)
#pragma unroll
            for (int mt = 0; mt < 2; mt++)
                mma_tf32(d[mt][nt], a[mt], bf[nt]);
    }

    // epilogue: bias, pool over center rows (within warp), stats
    int cent = m0 + wr;
#pragma unroll
    for (int nt = 0; nt < 4; nt++){
        int c0 = wc*32 + nt*8 + 2*tig;
        float bb0 = b2[c0], bb1 = b2[c0+1];
        float y00a = d[0][nt].x + bb0, y01a = d[0][nt].y + bb1;
        float y10a = d[0][nt].z + bb0, y11a = d[0][nt].w + bb1;
        float y00b = d[1][nt].x + bb0, y01b = d[1][nt].y + bb1;
        float y10b = d[1][nt].z + bb0, y11b = d[1][nt].w + bb1;
        float mx0 = fmaxf(fmaxf(y00a, y10a), fmaxf(y00b, y10b));
        float mx1 = fmaxf(fmaxf(y01a, y11a), fmaxf(y01b, y11b));
        float mn0 = fminf(fminf(y00a, y10a), fminf(y00b, y10b));
        float mn1 = fminf(fminf(y01a, y11a), fminf(y01b, y11b));
        float s0 = y00a + y10a + y00b + y10b;
        float s1v = y01a + y11a + y01b + y11b;
        float q0 = y00a*y00a + y10a*y10a + y00b*y00b + y10b*y10b;
        float q1v = y01a*y01a + y11a*y11a + y01b*y01b + y11b*y11b;
#pragma unroll
        for (int off = 16; off >= 4; off >>= 1){
            mx0 = fmaxf(mx0, __shfl_down_sync(0xffffffffu, mx0, off));
            mx1 = fmaxf(mx1, __shfl_down_sync(0xffffffffu, mx1, off));
            mn0 = fminf(mn0, __shfl_down_sync(0xffffffffu, mn0, off));
            mn1 = fminf(mn1, __shfl_down_sync(0xffffffffu, mn1, off));
            s0  += __shfl_down_sync(0xffffffffu, s0,  off);
            s1v += __shfl_down_sync(0xffffffffu, s1v, off);
            q0  += __shfl_down_sync(0xffffffffu, q0,  off);
            q1v += __shfl_down_sync(0xffffffffu, q1v, off);
        }
        if (g == 0){
            g_mx[(size_t)cent*128 + c0]   = mx0;
            g_mx[(size_t)cent*128 + c0+1] = mx1;
            g_mn[(size_t)cent*128 + c0]   = mn0;
            g_mn[(size_t)cent*128 + c0+1] = mn1;
            atomicAdd(&ssum[c0], s0);   atomicAdd(&ssum[c0+1], s1v);
            atomicAdd(&ssq[c0],  q0);   atomicAdd(&ssq[c0+1],  q1v);
        }
    }
    __syncthreads();
    if (tid < 128){
        int slot = blockIdx.x & 31;
        atomicAdd(&g_stats[SUM2 + tid*32 + slot], ssum[tid]);
        atomicAdd(&g_stats[SQ2  + tid*32 + slot], ssq[tid]);
    }
}

// ---------------- final: BN2+ReLU on pooled extremum ----------------
__global__ void out_kernel(float* __restrict__ out){
    int i = blockIdx.x*256 + threadIdx.x;   // NCTR_TOT*128
    int c = i & 127;
    float a = g_aff[A2 + c];
    float v = (a >= 0.f) ? g_mx[i] : g_mn[i];
    out[OUT_XYZ_ELEMS + i] = fmaxf(fmaf(a, v, g_aff[C2A + c]), 0.f);
}

// ---------------- host launcher ----------------
extern "C" void kernel_launch(void* const* d_in, const int* in_sizes, int n_in,
                              void* d_out, int out_size){
    const float* xyz   = (const float*)d_in[0];
    const float* feat  = (const float*)d_in[1];
    const float* w0 = (const float*)d_in[2];
    const float* b0 = (const float*)d_in[3];
    const float* g0 = (const float*)d_in[4];
    const float* be0 = (const float*)d_in[5];
    const float* w1 = (const float*)d_in[6];
    const float* b1 = (const float*)d_in[7];
    const float* g1 = (const float*)d_in[8];
    const float* be1 = (const float*)d_in[9];
    const float* w2 = (const float*)d_in[10];
    const float* b2 = (const float*)d_in[11];
    const float* g2 = (const float*)d_in[12];
    const float* be2 = (const float*)d_in[13];
    float* out = (float*)d_out;

    static const int MEGA_SMEM = (12288 + 64) * 4;                      // ~49.4 KB
    static const int L1_SMEM  = (128*P1 + 64*P1)*4 + 128*4 + 128*4;     // ~53.2 KB
    static const int L2_SMEM  = (64*P2 + 128*P2)*4 + 256*4;             // ~53.2 KB
    cudaFuncSetAttribute(mega_kernel, cudaFuncAttributeMaxDynamicSharedMemorySize, MEGA_SMEM);
    cudaFuncSetAttribute(l1_kernel,  cudaFuncAttributeMaxDynamicSharedMemorySize, L1_SMEM);
    cudaFuncSetAttribute(l2_kernel,  cudaFuncAttributeMaxDynamicSharedMemorySize, L2_SMEM);

    mega_kernel<<<FPS_NB + G_NB + BQ_NB, 256, MEGA_SMEM>>>(xyz, feat, w0, b0, out);
    fin_kernel<<<2, 1024>>>(g0, be0, SUM0, SQ0, A0, C0A, 64);
    l1_kernel<<<NCTR_TOT/4, 256, L1_SMEM>>>(w1, b1);
    fin_kernel<<<2, 1024>>>(g1, be1, SUM1, SQ1, A1, C1A, 64);
    l2_kernel<<<NCTR_TOT/2, 256, L2_SMEM>>>(w2, b2);
    fin_kernel<<<4, 1024>>>(g2, be2, SUM2, SQ2, A2, C2A, 128);
    out_kernel<<<NCTR_TOT*128/256, 256>>>(out);
}